// round 16
// baseline (speedup 1.0000x reference)
#include <cuda_runtime.h>
#include <cuda_bf16.h>
#include <cstdint>

#define SCALE       0.35355339059327373f   // 64^(-1/4)
#define INV_SQRT_M  0.08838834764831843f   // 1/sqrt(128)
#define EPS_PHI     1e-4f
#define EPS_DEN     1e-6f

#define BH    64        // B*H = 4*16
#define Nn    4096
#define Dd    64
#define Mm    128
#define CH    128       // chunk length
#define NC    32        // chunks per head
#define NTOK  (BH*Nn)   // 262144
#define NBT   (NTOK/CH) // 2048 token-chunks

typedef unsigned long long u64;
typedef unsigned int u32;
typedef unsigned short u16;

// ---------------- warp MMA helpers ----------------
__device__ __forceinline__ u32 s2u(const void* p) {
    u32 a; asm("{ .reg .u64 t; cvta.to.shared.u64 t, %1; cvt.u32.u64 %0, t; }"
               : "=r"(a) : "l"(p));
    return a;
}
__device__ __forceinline__ void ldsm4(u32& r0, u32& r1, u32& r2, u32& r3, u32 addr) {
    asm volatile("ldmatrix.sync.aligned.m8n8.x4.shared.b16 {%0,%1,%2,%3}, [%4];"
                 : "=r"(r0), "=r"(r1), "=r"(r2), "=r"(r3) : "r"(addr));
}
__device__ __forceinline__ void ldsm2(u32& r0, u32& r1, u32 addr) {
    asm volatile("ldmatrix.sync.aligned.m8n8.x2.shared.b16 {%0,%1}, [%2];"
                 : "=r"(r0), "=r"(r1) : "r"(addr));
}
__device__ __forceinline__ void ldsm2t(u32& r0, u32& r1, u32 addr) {
    asm volatile("ldmatrix.sync.aligned.m8n8.x2.trans.shared.b16 {%0,%1}, [%2];"
                 : "=r"(r0), "=r"(r1) : "r"(addr));
}
__device__ __forceinline__ void mma16816(float* d, u32 a0, u32 a1, u32 a2, u32 a3,
                                         u32 b0, u32 b1) {
    asm volatile("mma.sync.aligned.m16n8k16.row.col.f32.bf16.bf16.f32 "
                 "{%0,%1,%2,%3}, {%4,%5,%6,%7}, {%8,%9}, {%0,%1,%2,%3};"
                 : "+f"(d[0]), "+f"(d[1]), "+f"(d[2]), "+f"(d[3])
                 : "r"(a0), "r"(a1), "r"(a2), "r"(a3), "r"(b0), "r"(b1));
}

// bf16 split
__device__ __forceinline__ u16 bf16h(float x) {
    u16 u; asm("cvt.rn.bf16.f32 %0, %1;" : "=h"(u) : "f"(x)); return u;
}
__device__ __forceinline__ float bf2f(u16 u) {
    float f; asm("cvt.f32.bf16 %0, %1;" : "=f"(f) : "h"(u)); return f;
}
__device__ __forceinline__ void split2(float x, u16& h, u16& l) {
    h = bf16h(x); l = bf16h(x - bf2f(h));
}

// Tile row strides (bytes): 136-half rows, 72-half rows
#define SR  272
#define SR1 144
__device__ __forceinline__ u32 a_addr_s(u32 base, int m0, int k0, int lane, int srb) {
    int r  = m0 + (lane & 7) + ((lane >> 3) & 1) * 8;
    int kc = k0 + (lane >> 4) * 8;
    return base + r * srb + kc * 2;
}
__device__ __forceinline__ u32 b_addr_s(u32 base, int n0, int k0, int lane, int srb) {
    int r  = n0 + (lane & 7);
    int kc = k0 + ((lane >> 3) & 1) * 8;
    return base + r * srb + kc * 2;
}
__device__ __forceinline__ u32 a_addr(u32 base, int m0, int k0, int lane) {
    return a_addr_s(base, m0, k0, lane, SR);
}
__device__ __forceinline__ u32 b_addr(u32 base, int n0, int k0, int lane) {
    return b_addr_s(base, n0, k0, lane, SR);
}
// trans-B address: storage [k][n] row-major
__device__ __forceinline__ u32 bt_addr(u32 base, int n0, int k0, int lane) {
    int l8 = lane & 7, g = (lane >> 3) & 1;
    return base + (u32)(k0 + g*8 + l8) * SR + (u32)n0 * 2;
}

// Scratch
__device__ float d_phik[(size_t)NTOK*Mm];     // lp
__device__ float d_S[(size_t)BH*NC*Mm*Dd];    // S'^T then S_prev^T
__device__ float d_zz[BH*NC*Mm];              // z' then z_prev
__device__ float d_vsum[BH*NC*Dd];            // per-chunk sum of V, then unused
__device__ float d_bmax[NBT];
__device__ float d_gmax;

// ---------------------------------------------------------------------------
// K12 fused: per chunk — proj GEMM -> lp (gmem, for K4) + bmax; exp(lp)
// (UNSHIFTED; no gmax dependency) split into PK tiles; S'^T = V^T·e^lp GEMM;
// z' col sums; Vsum. Scan applies cg = exp(-gmax)/sqrt(M) and eps terms.
// ---------------------------------------------------------------------------
#define F_SSP 0
#define F_SS  8192
#define F_RED 8704
#define F_VP  9728
#define F_XH  10752
#define F_XL  (F_XH + 18432)
#define F_OH  (F_XL + 18432)
#define F_OL  (F_OH + 18432)
#define F_PKH (F_OL + 18432)        // 84480
#define F_PKL (F_PKH + 34816)
#define F_VTH (F_PKL + 34816)       // 154112
#define F_VTL (F_VTH + 17408)
#define F_ZP  (F_VTL + 17408)       // 188928
#define SMFT  (F_ZP + 1024)         // 189952 B

__global__ __launch_bounds__(256) void k_fused(const float* __restrict__ kg,
                                               const float* __restrict__ omg,
                                               const float* __restrict__ vg) {
    extern __shared__ char smc[];
    const u32 sb = s2u(smc);
    float* ssp = (float*)(smc + F_SSP);
    float* ss  = (float*)(smc + F_SS);
    float* red = (float*)(smc + F_RED);
    float* vp  = (float*)(smc + F_VP);
    float* zp  = (float*)(smc + F_ZP);

    const int tb = blockIdx.x;
    const float* xg = kg + (size_t)tb * CH * Dd;
    const size_t tok0 = (size_t)tb * CH;
    const int tid = threadIdx.x, wid = tid >> 5, lane = tid & 31;

    // ---- stage k (scaled, split, norm partials) + omega ----
    #pragma unroll
    for (int it = 0; it < 8; it++) {
        int f4g = it*256 + tid;
        int r = f4g >> 4, c4 = (f4g & 15) * 4;
        u32 off = (u32)r * SR1 + (u32)c4 * 2;
        float4 t = *reinterpret_cast<const float4*>(xg + r*Dd + c4);
        t.x *= SCALE; t.y *= SCALE; t.z *= SCALE; t.w *= SCALE;
        ssp[f4g] = t.x*t.x + t.y*t.y + t.z*t.z + t.w*t.w;
        u16 h0,l0,h1,l1,h2,l2,h3,l3;
        split2(t.x,h0,l0); split2(t.y,h1,l1); split2(t.z,h2,l2); split2(t.w,h3,l3);
        *(u32*)(smc+F_XH+off)   = (u32)h0 | ((u32)h1<<16);
        *(u32*)(smc+F_XH+off+4) = (u32)h2 | ((u32)h3<<16);
        *(u32*)(smc+F_XL+off)   = (u32)l0 | ((u32)l1<<16);
        *(u32*)(smc+F_XL+off+4) = (u32)l2 | ((u32)l3<<16);
        float4 w = *reinterpret_cast<const float4*>(omg + (size_t)f4g * 4);
        split2(w.x,h0,l0); split2(w.y,h1,l1); split2(w.z,h2,l2); split2(w.w,h3,l3);
        *(u32*)(smc+F_OH+off)   = (u32)h0 | ((u32)h1<<16);
        *(u32*)(smc+F_OH+off+4) = (u32)h2 | ((u32)h3<<16);
        *(u32*)(smc+F_OL+off)   = (u32)l0 | ((u32)l1<<16);
        *(u32*)(smc+F_OL+off+4) = (u32)l2 | ((u32)l3<<16);
    }
    // ---- stage V^T [64][128] (transposed gather, split) ----
    #pragma unroll
    for (int it = 0; it < 4; it++) {
        int t4 = it*256 + tid;                 // 0..1023
        int jp = t4 >> 4, dg = (t4 & 15) << 2;
        float4 va = *reinterpret_cast<const float4*>(vg + (tok0 + 2*jp)*Dd + dg);
        float4 vb = *reinterpret_cast<const float4*>(vg + (tok0 + 2*jp + 1)*Dd + dg);
        float fa[4] = {va.x, va.y, va.z, va.w};
        float fb[4] = {vb.x, vb.y, vb.z, vb.w};
        #pragma unroll
        for (int e = 0; e < 4; e++) {
            u16 ha,la,hb,lb;
            split2(fa[e], ha, la); split2(fb[e], hb, lb);
            u32 off = (u32)(dg+e) * SR + (u32)jp * 4;
            *(u32*)(smc+F_VTH+off) = (u32)ha | ((u32)hb<<16);
            *(u32*)(smc+F_VTL+off) = (u32)la | ((u32)lb<<16);
        }
    }
    __syncthreads();
    if (tid < 128) {
        float s = 0.f;
        #pragma unroll
        for (int j = 0; j < 16; j++) s += ssp[tid*16 + j];
        ss[tid] = 0.5f * s;
    }
    // Vsum partials from V^T tiles: thread t: d = t&63, quarter = t>>6
    {
        int d = tid & 63, qq = tid >> 6;
        float s = 0.f;
        #pragma unroll 8
        for (int i = 0; i < 32; i++) {
            u32 off = (u32)d * SR + (u32)(qq*32 + i) * 2;
            s += bf2f(*(u16*)(smc+F_VTH+off)) + bf2f(*(u16*)(smc+F_VTL+off));
        }
        vp[tid] = s;
    }
    __syncthreads();

    // ---- proj GEMM: lp rows i0..i0+15 ----
    const int i0 = wid * 16;
    float acc[16][4];
    #pragma unroll
    for (int nt = 0; nt < 16; nt++)
        #pragma unroll
        for (int e = 0; e < 4; e++) acc[nt][e] = 0.f;

    #pragma unroll
    for (int kk = 0; kk < 4; kk++) {
        int k0 = kk * 16;
        u32 xh0,xh1,xh2,xh3, xl0,xl1,xl2,xl3;
        ldsm4(xh0,xh1,xh2,xh3, a_addr_s(sb+F_XH, i0, k0, lane, SR1));
        ldsm4(xl0,xl1,xl2,xl3, a_addr_s(sb+F_XL, i0, k0, lane, SR1));
        #pragma unroll
        for (int nt = 0; nt < 16; nt++) {
            u32 oh0,oh1, ol0,ol1;
            ldsm2(oh0,oh1, b_addr_s(sb+F_OH, nt*8, k0, lane, SR1));
            ldsm2(ol0,ol1, b_addr_s(sb+F_OL, nt*8, k0, lane, SR1));
            mma16816(acc[nt], xh0,xh1,xh2,xh3, oh0,oh1);
            mma16816(acc[nt], xh0,xh1,xh2,xh3, ol0,ol1);
            mma16816(acc[nt], xl0,xl1,xl2,xl3, oh0,oh1);
        }
    }

    // ---- lp -> gmem + bmax; exp(lp) split -> PK tiles [i][m] ----
    const int m1 = i0 + (lane >> 2);
    const int m2 = m1 + 8;
    {
        const float s1 = ss[m1], s2 = ss[m2];
        float bm = -3.0e38f;
        float* og = d_phik + tok0 * Mm;
        #pragma unroll
        for (int nt = 0; nt < 16; nt++) {
            int jj = nt*8 + 2*(lane & 3);
            float2 t1, t2;
            t1.x = acc[nt][0] - s1; t1.y = acc[nt][1] - s1;
            t2.x = acc[nt][2] - s2; t2.y = acc[nt][3] - s2;
            bm = fmaxf(bm, fmaxf(fmaxf(t1.x, t1.y), fmaxf(t2.x, t2.y)));
            *reinterpret_cast<float2*>(og + (size_t)m1*Mm + jj) = t1;
            *reinterpret_cast<float2*>(og + (size_t)m2*Mm + jj) = t2;
            float e0 = __expf(t1.x), e1 = __expf(t1.y);
            float e2 = __expf(t2.x), e3 = __expf(t2.y);
            u16 h0,l0,h1,l1;
            split2(e0, h0, l0); split2(e1, h1, l1);
            u32 off = (u32)m1 * SR + (u32)jj * 2;
            *(u32*)(smc+F_PKH+off) = (u32)h0 | ((u32)h1<<16);
            *(u32*)(smc+F_PKL+off) = (u32)l0 | ((u32)l1<<16);
            split2(e2, h0, l0); split2(e3, h1, l1);
            off = (u32)m2 * SR + (u32)jj * 2;
            *(u32*)(smc+F_PKH+off) = (u32)h0 | ((u32)h1<<16);
            *(u32*)(smc+F_PKL+off) = (u32)l0 | ((u32)l1<<16);
        }
        red[tid] = bm;
    }
    __syncthreads();
    for (int s = 128; s > 0; s >>= 1) {
        if (tid < s) red[tid] = fmaxf(red[tid], red[tid+s]);
        __syncthreads();
    }
    if (tid == 0) d_bmax[tb] = red[0];

    // ---- z' column sums from PK tiles ----
    {
        int m = tid & 127, ih = tid >> 7;
        float s = 0.f;
        int ibase = ih * 64;
        #pragma unroll 8
        for (int i = 0; i < 64; i++) {
            u32 off = (u32)(ibase + i) * SR + (u32)m * 2;
            s += bf2f(*(u16*)(smc+F_PKH+off)) + bf2f(*(u16*)(smc+F_PKL+off));
        }
        zp[tid] = s;
    }
    __syncthreads();
    if (tid < 128) d_zz[tb*Mm + tid] = zp[tid] + zp[tid + 128];
    if (tid < 64)  d_vsum[tb*Dd + tid] = vp[tid] + vp[tid+64] + vp[tid+128] + vp[tid+192];

    // ---- S'-GEMM: S'^T = V^T . e^lp ----
    const int dt = wid >> 1, mh = wid & 1;
    const int d0 = dt * 16;
    float sacc[8][4];
    #pragma unroll
    for (int t = 0; t < 8; t++)
        #pragma unroll
        for (int e = 0; e < 4; e++) sacc[t][e] = 0.f;

    for (int kk = 0; kk < 8; kk++) {
        int k0 = kk * 16;
        u32 ah0,ah1,ah2,ah3, al0,al1,al2,al3;
        ldsm4(ah0,ah1,ah2,ah3, a_addr(sb+F_VTH, d0, k0, lane));
        ldsm4(al0,al1,al2,al3, a_addr(sb+F_VTL, d0, k0, lane));
        #pragma unroll
        for (int t = 0; t < 8; t++) {
            int n0 = (mh*8 + t) * 8;
            u32 bh0,bh1, bl0,bl1;
            ldsm2t(bh0,bh1, bt_addr(sb+F_PKH, n0, k0, lane));
            ldsm2t(bl0,bl1, bt_addr(sb+F_PKL, n0, k0, lane));
            mma16816(sacc[t], ah0,ah1,ah2,ah3, bh0,bh1);
            mma16816(sacc[t], ah0,ah1,ah2,ah3, bl0,bl1);
            mma16816(sacc[t], al0,al1,al2,al3, bh0,bh1);
        }
    }

    float* SgT = d_S + (size_t)tb * (Mm*Dd);
    const int d1 = d0 + (lane >> 2), d2 = d1 + 8;
    #pragma unroll
    for (int t = 0; t < 8; t++) {
        int m = (mh*8 + t)*8 + 2*(lane & 3);
        float2 t1 = { sacc[t][0], sacc[t][1] };
        float2 t2 = { sacc[t][2], sacc[t][3] };
        *reinterpret_cast<float2*>(SgT + d1*Mm + m) = t1;
        *reinterpret_cast<float2*>(SgT + d2*Mm + m) = t2;
    }
}

__global__ __launch_bounds__(256) void k_gmax() {
    __shared__ float red[256];
    const int tid = threadIdx.x;
    float m = -3.0e38f;
    for (int i = tid; i < NBT; i += 256) m = fmaxf(m, d_bmax[i]);
    red[tid] = m;
    __syncthreads();
    for (int s = 128; s > 0; s >>= 1) {
        if (tid < s) red[tid] = fmaxf(red[tid], red[tid+s]);
        __syncthreads();
    }
    if (tid == 0) d_gmax = red[0];
}

// ---------------------------------------------------------------------------
// K3: exclusive prefix over 32 chunks + affine fix-up:
//  S_prev = cg*prefix(S') + eps*prefix(Vsum);  z_prev = cg*prefix(z') + eps*128*c
// ---------------------------------------------------------------------------
__global__ __launch_bounds__(256) void k_scan() {
    const int gid = blockIdx.x * 256 + threadIdx.x;
    const float cg = __expf(-d_gmax) * INV_SQRT_M;
    if (blockIdx.x < 2048) {
        const int bh = gid >> 13;
        const int e  = gid & 8191;
        const int d  = e >> 7;
        const size_t p = (size_t)bh * NC * (Mm*Dd) + e;
        const float* vs = d_vsum + (size_t)bh * NC * Dd + d;
        float v[NC], vv[NC];
        #pragma unroll
        for (int c = 0; c < NC; c++) v[c]  = d_S[p + (size_t)c * (Mm*Dd)];
        #pragma unroll
        for (int c = 0; c < NC; c++) vv[c] = vs[c * Dd];
        float acc = 0.f, vacc = 0.f;
        #pragma unroll
        for (int c = 0; c < NC; c++) {
            d_S[p + (size_t)c * (Mm*Dd)] = cg * acc + EPS_PHI * vacc;
            acc += v[c]; vacc += vv[c];
        }
    } else {
        const int idx = gid - 2048*256;
        const int bh = idx >> 7, m = idx & 127;
        const size_t p = (size_t)bh * NC * Mm + m;
        float v[NC];
        #pragma unroll
        for (int c = 0; c < NC; c++) v[c] = d_zz[p + c*Mm];
        float acc = 0.f;
        #pragma unroll
        for (int c = 0; c < NC; c++) {
            d_zz[p + c*Mm] = cg * acc + EPS_PHI * (float)(CH * c);
            acc += v[c];
        }
    }
}

// ---------------------------------------------------------------------------
// K4 (warp-MMA, 512 threads): exact R15 (q-proj fused; lp -> exp staging)
// ---------------------------------------------------------------------------
#define OF_RM  0
#define SQ_HI  1024
#define SQ_LO  (SQ_HI + 34816)
#define SK_HI  (SQ_LO + 34816)
#define SK_LO  (SK_HI + 34816)
#define SV_HI  (SK_LO + 34816)
#define SV_LO  (SV_HI + 19584)
#define SS_HI  (SV_LO + 19584)
#define SS_LO  (SS_HI + 19584)
#define SM4T   (SS_LO + 19584)   // 218624 bytes

__global__ __launch_bounds__(512) void k_out_mma(const float* __restrict__ qg,
                                                 const float* __restrict__ omg,
                                                 const float* __restrict__ vg,
                                                 float* __restrict__ outg) {
    extern __shared__ char smc[];
    const u32 sb = s2u(smc);
    float* rm_s  = (float*)(smc + OF_RM);
    const int tid = threadIdx.x, wid = tid >> 5, lane = tid & 31;
    const int pid = wid & 7, half = wid >> 3;
    const int bid = blockIdx.x, bh = bid >> 5, c = bid & 31;
    const size_t tok0 = (size_t)bh * Nn + (size_t)c * CH;
    const float gm = d_gmax;

    const float* xg = qg + tok0 * Dd;
    #pragma unroll
    for (int it = 0; it < 4; it++) {
        int f4g = it*512 + tid;
        int r = f4g >> 4, c4 = (f4g & 15) * 4;
        u32 off = (u32)r * SR + (u32)c4 * 2;
        float4 t = *reinterpret_cast<const float4*>(xg + r*Dd + c4);
        t.x *= SCALE; t.y *= SCALE; t.z *= SCALE; t.w *= SCALE;
        u16 h0,l0,h1,l1,h2,l2,h3,l3;
        split2(t.x,h0,l0); split2(t.y,h1,l1); split2(t.z,h2,l2); split2(t.w,h3,l3);
        *(u32*)(smc+SQ_HI+off)   = (u32)h0 | ((u32)h1<<16);
        *(u32*)(smc+SQ_HI+off+4) = (u32)h2 | ((u32)h3<<16);
        *(u32*)(smc+SQ_LO+off)   = (u32)l0 | ((u32)l1<<16);
        *(u32*)(smc+SQ_LO+off+4) = (u32)l2 | ((u32)l3<<16);
        float4 w = *reinterpret_cast<const float4*>(omg + (size_t)f4g * 4);
        split2(w.x,h0,l0); split2(w.y,h1,l1); split2(w.z,h2,l2); split2(w.w,h3,l3);
        *(u32*)(smc+SK_HI+off)   = (u32)h0 | ((u32)h1<<16);
        *(u32*)(smc+SK_HI+off+4) = (u32)h2 | ((u32)h3<<16);
        *(u32*)(smc+SK_LO+off)   = (u32)l0 | ((u32)l1<<16);
        *(u32*)(smc+SK_LO+off+4) = (u32)l2 | ((u32)l3<<16);
    }
    __syncthreads();

    {
        const int prow = pid * 16;
        float pacc[8][4];
        #pragma unroll
        for (int t = 0; t < 8; t++)
            #pragma unroll
            for (int e = 0; e < 4; e++) pacc[t][e] = 0.f;

        #pragma unroll
        for (int kk = 0; kk < 4; kk++) {
            int k0 = kk * 16;
            u32 xh0,xh1,xh2,xh3, xl0,xl1,xl2,xl3;
            ldsm4(xh0,xh1,xh2,xh3, a_addr(sb+SQ_HI, prow, k0, lane));
            ldsm4(xl0,xl1,xl2,xl3, a_addr(sb+SQ_LO, prow, k0, lane));
            #pragma unroll
            for (int t = 0; t < 8; t++) {
                int nt = half*8 + t;
                u32 oh0,oh1, ol0,ol1;
                ldsm2(oh0,oh1, b_addr(sb+SK_HI, nt*8, k0, lane));
                ldsm2(ol0,ol1, b_addr(sb+SK_LO, nt*8, k0, lane));
                mma16816(pacc[t], xh0,xh1,xh2,xh3, oh0,oh1);
                mma16816(pacc[t], xh0,xh1,xh2,xh3, ol0,ol1);
                mma16816(pacc[t], xl0,xl1,xl2,xl3, oh0,oh1);
            }
        }

        const int m1 = prow + (lane >> 2);
        const int m2 = m1 + 8;
        float rm1 = -3.0e38f, rm2 = -3.0e38f;
        #pragma unroll
        for (int t = 0; t < 8; t++) {
            rm1 = fmaxf(rm1, fmaxf(pacc[t][0], pacc[t][1]));
            rm2 = fmaxf(rm2, fmaxf(pacc[t][2], pacc[t][3]));
        }
        rm1 = fmaxf(rm1, __shfl_xor_sync(0xFFFFFFFFu, rm1, 1));
        rm1 = fmaxf(rm1, __shfl_xor_sync(0xFFFFFFFFu, rm1, 2));
        rm2 = fmaxf(rm2, __shfl_xor_sync(0xFFFFFFFFu, rm2, 1));
        rm2 = fmaxf(rm2, __shfl_xor_sync(0xFFFFFFFFu, rm2, 2));
        if ((lane & 3) == 0) {
            rm_s[m1*2 + half] = rm1;
            rm_s[m2*2 + half] = rm2;
        }
        __syncthreads();
        rm1 = fmaxf(rm_s[m1*2], rm_s[m1*2 + 1]);
        rm2 = fmaxf(rm_s[m2*2], rm_s[m2*2 + 1]);

        #pragma unroll
        for (int t = 0; t < 8; t++) {
            int jj = (half*8 + t)*8 + 2*(lane & 3);
            float p0 = __expf(pacc[t][0]-rm1)*INV_SQRT_M + EPS_PHI;
            float p1 = __expf(pacc[t][1]-rm1)*INV_SQRT_M + EPS_PHI;
            float p2 = __expf(pacc[t][2]-rm2)*INV_SQRT_M + EPS_PHI;
            float p3 = __expf(pacc[t][3]-rm2)*INV_SQRT_M + EPS_PHI;
            u16 h0,l0,h1,l1;
            split2(p0, h0, l0); split2(p1, h1, l1);
            u32 off = (u32)m1 * SR + (u32)jj * 2;
            *(u32*)(smc+SQ_HI+off) = (u32)h0 | ((u32)h1<<16);
            *(u32*)(smc+SQ_LO+off) = (u32)l0 | ((u32)l1<<16);
            split2(p2, h0, l0); split2(p3, h1, l1);
            off = (u32)m2 * SR + (u32)jj * 2;
            *(u32*)(smc+SQ_HI+off) = (u32)h0 | ((u32)h1<<16);
            *(u32*)(smc+SQ_LO+off) = (u32)l0 | ((u32)l1<<16);
        }
    }
    __syncthreads();

    const float* pkg = d_phik + tok0 * Mm;
    #pragma unroll
    for (int it = 0; it < 8; it++) {
        int idx = (it*512 + tid) * 4;
        int r = idx >> 7, cc = idx & 127;
        u32 off = (u32)r * SR + (u32)cc * 2;
        float4 t = *reinterpret_cast<const float4*>(pkg + idx);
        t.x = __expf(t.x-gm)*INV_SQRT_M + EPS_PHI;
        t.y = __expf(t.y-gm)*INV_SQRT_M + EPS_PHI;
        t.z = __expf(t.z-gm)*INV_SQRT_M + EPS_PHI;
        t.w = __expf(t.w-gm)*INV_SQRT_M + EPS_PHI;
        u16 h0,l0,h1,l1,h2,l2,h3,l3;
        split2(t.x,h0,l0); split2(t.y,h1,l1); split2(t.z,h2,l2); split2(t.w,h3,l3);
        *(u32*)(smc+SK_HI+off)   = (u32)h0 | ((u32)h1<<16);
        *(u32*)(smc+SK_HI+off+4) = (u32)h2 | ((u32)h3<<16);
        *(u32*)(smc+SK_LO+off)   = (u32)l0 | ((u32)l1<<16);
        *(u32*)(smc+SK_LO+off+4) = (u32)l2 | ((u32)l3<<16);
    }

    #pragma unroll
    for (int it = 0; it < 2; it++) {
        int t4 = it*512 + tid;
        int jp = t4 >> 4, dg = (t4 & 15) << 2;
        float4 va = *reinterpret_cast<const float4*>(vg + (tok0 + 2*jp)*Dd + dg);
        float4 vb = *reinterpret_cast<const float4*>(vg + (tok0 + 2*jp + 1)*Dd + dg);
        float fa[4] = {va.x, va.y, va.z, va.w};
        float fb[4] = {vb.x, vb.y, vb.z, vb.w};
        #pragma unroll
        for (int e = 0; e < 4; e++) {
            u16 ha,la,hb,lb;
            split2(fa[e], ha, la); split2(fb[e], hb, lb);
            u32 off = (u32)(dg+e) * SR + (u32)jp * 4;
            *(u32*)(smc+SV_HI+off) = (u32)ha | ((u32)hb<<16);
            *(u32*)(smc+SV_LO+off) = (u32)la | ((u32)lb<<16);
        }
    }
    {
        const float* SgT = d_S + (size_t)(bh*NC + c) * (Mm*Dd);
        #pragma unroll
        for (int it = 0; it < 4; it++) {
            int idx = (it*512 + tid) * 4;
            int d = idx >> 7, m = idx & 127;
            u32 off = (u32)d * SR + (u32)m * 2;
            float4 t = *reinterpret_cast<const float4*>(SgT + idx);
            u16 h0,l0,h1,l1,h2,l2,h3,l3;
            split2(t.x,h0,l0); split2(t.y,h1,l1); split2(t.z,h2,l2); split2(t.w,h3,l3);
            *(u32*)(smc+SS_HI+off)   = (u32)h0 | ((u32)h1<<16);
            *(u32*)(smc+SS_HI+off+4) = (u32)h2 | ((u32)h3<<16);
            *(u32*)(smc+SS_LO+off)   = (u32)l0 | ((u32)l1<<16);
            *(u32*)(smc+SS_LO+off+4) = (u32)l2 | ((u32)l3<<16);
        }
    }
    if (tid < 64) {
        int cp = tid * 2;
        u32 off = 64u * SR + (u32)tid * 4;
        *(u32*)(smc+SV_HI+off) = 0x3F803F80u;
        *(u32*)(smc+SV_LO+off) = 0u;
        const float* zg = d_zz + (bh*NC + c) * Mm;
        u16 h0,l0,h1,l1;
        split2(zg[cp],   h0, l0);
        split2(zg[cp+1], h1, l1);
        *(u32*)(smc+SS_HI+off) = (u32)h0 | ((u32)h1<<16);
        *(u32*)(smc+SS_LO+off) = (u32)l0 | ((u32)l1<<16);
    }
    for (int t4 = tid; t4 < 7*64; t4 += 512) {
        int r = 65 + t4/64;
        u32 off = (u32)r * SR + (u32)(t4 % 64) * 4;
        *(u32*)(smc+SV_HI+off) = 0u;
        *(u32*)(smc+SV_LO+off) = 0u;
        *(u32*)(smc+SS_HI+off) = 0u;
        *(u32*)(smc+SS_LO+off) = 0u;
    }
    __syncthreads();

    const int ib = (pid < 4) ? pid : (7 - (pid - 4));
    const int i0 = ib * 16;

    float acc[8][4];
    #pragma unroll
    for (int s = 0; s < 8; s++)
        #pragma unroll
        for (int e = 0; e < 4; e++) acc[s][e] = 0.f;

    for (int kk = 0; kk < 8; kk++) {
        int k0 = kk * 16;
        u32 qh0,qh1,qh2,qh3, ql0,ql1,ql2,ql3;
        ldsm4(qh0,qh1,qh2,qh3, a_addr(sb+SQ_HI, i0, k0, lane));
        ldsm4(ql0,ql1,ql2,ql3, a_addr(sb+SQ_LO, i0, k0, lane));
        #pragma unroll
        for (int s = 0; s < 4; s++) {
            int np = 2*s + half;
            if (np <= ib) {
                #pragma unroll
                for (int tt = 0; tt < 2; tt++) {
                    int nt = 2*np + tt;
                    u32 bh0,bh1, bl0,bl1;
                    ldsm2(bh0,bh1, b_addr(sb+SK_HI, nt*8, k0, lane));
                    ldsm2(bl0,bl1, b_addr(sb+SK_LO, nt*8, k0, lane));
                    mma16816(acc[2*s+tt], qh0,qh1,qh2,qh3, bh0,bh1);
                    mma16816(acc[2*s+tt], qh0,qh1,qh2,qh3, bl0,bl1);
                    mma16816(acc[2*s+tt], ql0,ql1,ql2,ql3, bh0,bh1);
                }
            }
        }
    }

    __syncthreads();

    {
        const int m1 = i0 + (lane >> 2);
        const int m2 = m1 + 8;
        #pragma unroll
        for (int s = 0; s < 4; s++) {
            int np = 2*s + half;
            if (np <= ib) {
                #pragma unroll
                for (int tt = 0; tt < 2; tt++) {
                    int nt = 2*np + tt;
                    int jj = nt*8 + 2*(lane & 3);
                    float a0 = (jj     <= m1) ? acc[2*s+tt][0] : 0.f;
                    float a1 = (jj + 1 <= m1) ? acc[2*s+tt][1] : 0.f;
                    float a2 = (jj     <= m2) ? acc[2*s+tt][2] : 0.f;
                    float a3 = (jj + 1 <= m2) ? acc[2*s+tt][3] : 0.f;
                    u16 h0,l0,h1,l1;
                    split2(a0, h0, l0); split2(a1, h1, l1);
                    u32 off = (u32)m1 * SR + (u32)jj * 2;
                    *(u32*)(smc+SK_HI+off) = (u32)h0 | ((u32)h1<<16);
                    *(u32*)(smc+SK_LO+off) = (u32)l0 | ((u32)l1<<16);
                    split2(a2, h0, l0); split2(a3, h1, l1);
                    off = (u32)m2 * SR + (u32)jj * 2;
                    *(u32*)(smc+SK_HI+off) = (u32)h0 | ((u32)h1<<16);
                    *(u32*)(smc+SK_LO+off) = (u32)l0 | ((u32)l1<<16);
                }
            }
        }
    }
    __syncthreads();

    float o[5][4];
    #pragma unroll
    for (int s = 0; s < 5; s++)
        #pragma unroll
        for (int e = 0; e < 4; e++) o[s][e] = 0.f;
    const int ntbase = half * 4;

    for (int kk = 0; kk < 8; kk++) {
        int k0 = kk * 16;
        u32 qh0,qh1,qh2,qh3, ql0,ql1,ql2,ql3;
        ldsm4(qh0,qh1,qh2,qh3, a_addr(sb+SQ_HI, i0, k0, lane));
        ldsm4(ql0,ql1,ql2,ql3, a_addr(sb+SQ_LO, i0, k0, lane));
        const bool doA = (kk <= ib);
        u32 ah0=0,ah1=0,ah2=0,ah3=0, al0=0,al1=0,al2=0,al3=0;
        if (doA) {
            ldsm4(ah0,ah1,ah2,ah3, a_addr(sb+SK_HI, i0, k0, lane));
            ldsm4(al0,al1,al2,al3, a_addr(sb+SK_LO, i0, k0, lane));
        }
        #pragma unroll
        for (int t = 0; t < 4; t++) {
            int nt = ntbase + t;
            u32 sh0,sh1, sl0,sl1;
            ldsm2(sh0,sh1, b_addr(sb+SS_HI, nt*8, k0, lane));
            ldsm2(sl0,sl1, b_addr(sb+SS_LO, nt*8, k0, lane));
            mma16816(o[t], qh0,qh1,qh2,qh3, sh0,sh1);
            mma16816(o[t], qh0,qh1,qh2,qh3, sl0,sl1);
            mma16816(o[t], ql0,ql1,ql2,ql3, sh0,sh1);
            if (doA) {
                u32 vh0,vh1, vl0,vl1;
                ldsm2(vh0,vh1, b_addr(sb+SV_HI, nt*8, k0, lane));
                ldsm2(vl0,vl1, b_addr(sb+SV_LO, nt*8, k0, lane));
                mma16816(o[t], ah0,ah1,ah2,ah3, vh0,vh1);
                mma16816(o[t], ah0,ah1,ah2,ah3, vl0,vl1);
                mma16816(o[t], al0,al1,al2,al3, vh0,vh1);
            }
        }
        if (half == 1) {
            u32 sh0,sh1, sl0,sl1;
            ldsm2(sh0,sh1, b_addr(sb+SS_HI, 64, k0, lane));
            ldsm2(sl0,sl1, b_addr(sb+SS_LO, 64, k0, lane));
            mma16816(o[4], qh0,qh1,qh2,qh3, sh0,sh1);
            mma16816(o[4], qh0,qh1,qh2,qh3, sl0,sl1);
            mma16816(o[4], ql0,ql1,ql2,ql3, sh0,sh1);
            if (doA) {
                u32 vh0,vh1, vl0,vl1;
                ldsm2(vh0,vh1, b_addr(sb+SV_HI, 64, k0, lane));
                ldsm2(vl0,vl1, b_addr(sb+SV_LO, 64, k0, lane));
                mma16816(o[4], ah0,ah1,ah2,ah3, vh0,vh1);
                mma16816(o[4], ah0,ah1,ah2,ah3, vl0,vl1);
                mma16816(o[4], al0,al1,al2,al3, vh0,vh1);
            }
        }
    }

    if (half == 1 && (lane & 3) == 0) {
        rm_s[i0 + (lane >> 2)]     = 1.f / (o[4][0] + EPS_DEN);
        rm_s[i0 + 8 + (lane >> 2)] = 1.f / (o[4][2] + EPS_DEN);
    }
    __syncthreads();
    {
        const int m1 = i0 + (lane >> 2);
        const int m2 = m1 + 8;
        const float inv1 = rm_s[m1];
        const float inv2 = rm_s[m2];
        #pragma unroll
        for (int t = 0; t < 4; t++) {
            int n = (ntbase + t)*8 + 2*(lane & 3);
            float2 t1 = { o[t][0]*inv1, o[t][1]*inv1 };
            float2 t2 = { o[t][2]*inv2, o[t][3]*inv2 };
            *reinterpret_cast<float2*>(outg + (tok0 + m1)*Dd + n) = t1;
            *reinterpret_cast<float2*>(outg + (tok0 + m2)*Dd + n) = t2;
        }
    }
}

// ---------------------------------------------------------------------------

extern "C" void kernel_launch(void* const* d_in, const int* in_sizes, int n_in,
                              void* d_out, int out_size) {
    const float* q  = (const float*)d_in[0];
    const float* k  = (const float*)d_in[1];
    const float* v  = (const float*)d_in[2];
    const float* om = (const float*)d_in[3];
    float* out = (float*)d_out;

    cudaFuncSetAttribute(k_fused,   cudaFuncAttributeMaxDynamicSharedMemorySize, SMFT);
    cudaFuncSetAttribute(k_out_mma, cudaFuncAttributeMaxDynamicSharedMemorySize, SM4T);

    k_fused<<<NBT, 256, SMFT>>>(k, om, v);
    k_gmax<<<1, 256>>>();
    k_scan<<<2048 + 32, 256>>>();
    k_out_mma<<<NBT, 512, SM4T>>>(q, om, v, out);
}

// round 17
// speedup vs baseline: 1.0803x; 1.0803x over previous
#include <cuda_runtime.h>
#include <cuda_bf16.h>
#include <cstdint>

#define SCALE       0.35355339059327373f   // 64^(-1/4)
#define INV_SQRT_M  0.08838834764831843f   // 1/sqrt(128)
#define EPS_PHI     1e-4f
#define EPS_DEN     1e-6f

#define BH    64        // B*H = 4*16
#define Nn    4096
#define Dd    64
#define Mm    128
#define CH    128       // chunk length
#define NC    32        // chunks per head
#define NTOK  (BH*Nn)   // 262144
#define NBT   (NTOK/CH) // 2048 token-chunks

typedef unsigned long long u64;
typedef unsigned int u32;
typedef unsigned short u16;

// ---------------- warp MMA helpers ----------------
__device__ __forceinline__ u32 s2u(const void* p) {
    u32 a; asm("{ .reg .u64 t; cvta.to.shared.u64 t, %1; cvt.u32.u64 %0, t; }"
               : "=r"(a) : "l"(p));
    return a;
}
__device__ __forceinline__ void ldsm4(u32& r0, u32& r1, u32& r2, u32& r3, u32 addr) {
    asm volatile("ldmatrix.sync.aligned.m8n8.x4.shared.b16 {%0,%1,%2,%3}, [%4];"
                 : "=r"(r0), "=r"(r1), "=r"(r2), "=r"(r3) : "r"(addr));
}
__device__ __forceinline__ void ldsm2(u32& r0, u32& r1, u32 addr) {
    asm volatile("ldmatrix.sync.aligned.m8n8.x2.shared.b16 {%0,%1}, [%2];"
                 : "=r"(r0), "=r"(r1) : "r"(addr));
}
__device__ __forceinline__ void ldsm2t(u32& r0, u32& r1, u32 addr) {
    asm volatile("ldmatrix.sync.aligned.m8n8.x2.trans.shared.b16 {%0,%1}, [%2];"
                 : "=r"(r0), "=r"(r1) : "r"(addr));
}
__device__ __forceinline__ void mma16816(float* d, u32 a0, u32 a1, u32 a2, u32 a3,
                                         u32 b0, u32 b1) {
    asm volatile("mma.sync.aligned.m16n8k16.row.col.f32.bf16.bf16.f32 "
                 "{%0,%1,%2,%3}, {%4,%5,%6,%7}, {%8,%9}, {%0,%1,%2,%3};"
                 : "+f"(d[0]), "+f"(d[1]), "+f"(d[2]), "+f"(d[3])
                 : "r"(a0), "r"(a1), "r"(a2), "r"(a3), "r"(b0), "r"(b1));
}

// bf16 split
__device__ __forceinline__ u16 bf16h(float x) {
    u16 u; asm("cvt.rn.bf16.f32 %0, %1;" : "=h"(u) : "f"(x)); return u;
}
__device__ __forceinline__ float bf2f(u16 u) {
    float f; asm("cvt.f32.bf16 %0, %1;" : "=f"(f) : "h"(u)); return f;
}
__device__ __forceinline__ void split2(float x, u16& h, u16& l) {
    h = bf16h(x); l = bf16h(x - bf2f(h));
}

// Tile row strides (bytes)
#define SR  272
#define SR1 144
__device__ __forceinline__ u32 a_addr_s(u32 base, int m0, int k0, int lane, int srb) {
    int r  = m0 + (lane & 7) + ((lane >> 3) & 1) * 8;
    int kc = k0 + (lane >> 4) * 8;
    return base + r * srb + kc * 2;
}
__device__ __forceinline__ u32 b_addr_s(u32 base, int n0, int k0, int lane, int srb) {
    int r  = n0 + (lane & 7);
    int kc = k0 + ((lane >> 3) & 1) * 8;
    return base + r * srb + kc * 2;
}
__device__ __forceinline__ u32 a_addr(u32 base, int m0, int k0, int lane) {
    return a_addr_s(base, m0, k0, lane, SR);
}
__device__ __forceinline__ u32 b_addr(u32 base, int n0, int k0, int lane) {
    return b_addr_s(base, n0, k0, lane, SR);
}
// trans-B address: storage [k][n] row-major
__device__ __forceinline__ u32 bt_addr(u32 base, int n0, int k0, int lane) {
    int l8 = lane & 7, g = (lane >> 3) & 1;
    return base + (u32)(k0 + g*8 + l8) * SR + (u32)n0 * 2;
}

// Scratch
__device__ float d_phik[(size_t)NTOK*Mm];   // lp
__device__ float d_S[(size_t)BH*NC*Mm*Dd];  // S^T layout: [chunk][d=64][m=128]
__device__ float d_zz[BH*NC*Mm];
__device__ float d_bmax[NBT];
__device__ float d_gmax;

// ---------------------------------------------------------------------------
// K1 (warp-MMA, k-only): lp = (k*scale)@omega^T - 0.5||k*scale||^2  (R15)
// ---------------------------------------------------------------------------
#define P_SSP 0
#define P_SS  8192
#define P_RED 8704
#define P_XH  9728
#define P_XL  (P_XH + 18432)
#define P_OH  (P_XL + 18432)
#define P_OL  (P_OH + 18432)
#define SM1T  (P_OL + 18432)   // 83456 B

__global__ __launch_bounds__(256) void k_proj_mma(const float* __restrict__ kg,
                                                  const float* __restrict__ omg) {
    extern __shared__ char smc[];
    const u32 sb = s2u(smc);
    float* ssp = (float*)(smc + P_SSP);
    float* ss  = (float*)(smc + P_SS);
    float* red = (float*)(smc + P_RED);

    const int tb = blockIdx.x;
    const float* xg = kg + (size_t)tb * CH * Dd;
    const int tid = threadIdx.x, wid = tid >> 5, lane = tid & 31;

    #pragma unroll
    for (int it = 0; it < 8; it++) {
        int f4g = it*256 + tid;
        int r = f4g >> 4, c4 = (f4g & 15) * 4;
        u32 off = (u32)r * SR1 + (u32)c4 * 2;
        float4 t = *reinterpret_cast<const float4*>(xg + r*Dd + c4);
        t.x *= SCALE; t.y *= SCALE; t.z *= SCALE; t.w *= SCALE;
        ssp[f4g] = t.x*t.x + t.y*t.y + t.z*t.z + t.w*t.w;
        u16 h0,l0,h1,l1,h2,l2,h3,l3;
        split2(t.x,h0,l0); split2(t.y,h1,l1); split2(t.z,h2,l2); split2(t.w,h3,l3);
        *(u32*)(smc+P_XH+off)   = (u32)h0 | ((u32)h1<<16);
        *(u32*)(smc+P_XH+off+4) = (u32)h2 | ((u32)h3<<16);
        *(u32*)(smc+P_XL+off)   = (u32)l0 | ((u32)l1<<16);
        *(u32*)(smc+P_XL+off+4) = (u32)l2 | ((u32)l3<<16);
        float4 w = *reinterpret_cast<const float4*>(omg + (size_t)f4g * 4);
        split2(w.x,h0,l0); split2(w.y,h1,l1); split2(w.z,h2,l2); split2(w.w,h3,l3);
        *(u32*)(smc+P_OH+off)   = (u32)h0 | ((u32)h1<<16);
        *(u32*)(smc+P_OH+off+4) = (u32)h2 | ((u32)h3<<16);
        *(u32*)(smc+P_OL+off)   = (u32)l0 | ((u32)l1<<16);
        *(u32*)(smc+P_OL+off+4) = (u32)l2 | ((u32)l3<<16);
    }
    __syncthreads();
    if (tid < 128) {
        float s = 0.f;
        #pragma unroll
        for (int j = 0; j < 16; j++) s += ssp[tid*16 + j];
        ss[tid] = 0.5f * s;
    }
    __syncthreads();

    const int i0 = wid * 16;
    float acc[16][4];
    #pragma unroll
    for (int nt = 0; nt < 16; nt++)
        #pragma unroll
        for (int e = 0; e < 4; e++) acc[nt][e] = 0.f;

    #pragma unroll
    for (int kk = 0; kk < 4; kk++) {
        int k0 = kk * 16;
        u32 xh0,xh1,xh2,xh3, xl0,xl1,xl2,xl3;
        ldsm4(xh0,xh1,xh2,xh3, a_addr_s(sb+P_XH, i0, k0, lane, SR1));
        ldsm4(xl0,xl1,xl2,xl3, a_addr_s(sb+P_XL, i0, k0, lane, SR1));
        #pragma unroll
        for (int nt = 0; nt < 16; nt++) {
            u32 oh0,oh1, ol0,ol1;
            ldsm2(oh0,oh1, b_addr_s(sb+P_OH, nt*8, k0, lane, SR1));
            ldsm2(ol0,ol1, b_addr_s(sb+P_OL, nt*8, k0, lane, SR1));
            mma16816(acc[nt], xh0,xh1,xh2,xh3, oh0,oh1);
            mma16816(acc[nt], xh0,xh1,xh2,xh3, ol0,ol1);
            mma16816(acc[nt], xl0,xl1,xl2,xl3, oh0,oh1);
        }
    }

    const int m1 = i0 + (lane >> 2);
    const int m2 = m1 + 8;
    const size_t tok0 = (size_t)tb * CH;

    const float s1 = ss[m1], s2 = ss[m2];
    float bm = -3.0e38f;
    float* og = d_phik + tok0 * Mm;
    #pragma unroll
    for (int nt = 0; nt < 16; nt++) {
        int jj = nt*8 + 2*(lane & 3);
        float2 t1, t2;
        t1.x = acc[nt][0] - s1; t1.y = acc[nt][1] - s1;
        t2.x = acc[nt][2] - s2; t2.y = acc[nt][3] - s2;
        bm = fmaxf(bm, fmaxf(fmaxf(t1.x, t1.y), fmaxf(t2.x, t2.y)));
        *reinterpret_cast<float2*>(og + (size_t)m1*Mm + jj) = t1;
        *reinterpret_cast<float2*>(og + (size_t)m2*Mm + jj) = t2;
    }
    red[tid] = bm;
    __syncthreads();
    for (int s = 128; s > 0; s >>= 1) {
        if (tid < s) red[tid] = fmaxf(red[tid], red[tid+s]);
        __syncthreads();
    }
    if (tid == 0) d_bmax[tb] = red[0];
}

__global__ __launch_bounds__(256) void k_gmax() {
    __shared__ float red[256];
    const int tid = threadIdx.x;
    float m = -3.0e38f;
    for (int i = tid; i < NBT; i += 256) m = fmaxf(m, d_bmax[i]);
    red[tid] = m;
    __syncthreads();
    for (int s = 128; s > 0; s >>= 1) {
        if (tid < s) red[tid] = fmaxf(red[tid], red[tid+s]);
        __syncthreads();
    }
    if (tid == 0) d_gmax = red[0];
}

// ---------------------------------------------------------------------------
// K2 (warp-MMA): S^T[d,m] = sum_i V[i,d] * phik[i,m]  (R15)
// ---------------------------------------------------------------------------
#define Q_PKH 0
#define Q_PKL (Q_PKH + 34816)
#define Q_VTH (Q_PKL + 34816)
#define Q_VTL (Q_VTH + 17408)
#define Q_ZP  (Q_VTL + 17408)
#define SM2T  (Q_ZP + 1024)   // 105472 B

__global__ __launch_bounds__(256) void k_sums_mma(const float* __restrict__ vg) {
    extern __shared__ char smc[];
    const u32 sb = s2u(smc);
    float* zp = (float*)(smc + Q_ZP);
    const int tid = threadIdx.x, wid = tid >> 5, lane = tid & 31;
    const int bid = blockIdx.x, bh = bid >> 5, c = bid & 31;
    const size_t tok0 = (size_t)bh * Nn + (size_t)c * CH;
    const float gm = d_gmax;

    const float* pk = d_phik + tok0 * Mm;   // lp
    #pragma unroll
    for (int it = 0; it < 16; it++) {
        int idx = (it*256 + tid) * 4;
        int i = idx >> 7, m = idx & 127;
        u32 off = (u32)i * SR + (u32)m * 2;
        float4 t = *reinterpret_cast<const float4*>(pk + idx);
        t.x = __expf(t.x-gm)*INV_SQRT_M + EPS_PHI;
        t.y = __expf(t.y-gm)*INV_SQRT_M + EPS_PHI;
        t.z = __expf(t.z-gm)*INV_SQRT_M + EPS_PHI;
        t.w = __expf(t.w-gm)*INV_SQRT_M + EPS_PHI;
        u16 h0,l0,h1,l1,h2,l2,h3,l3;
        split2(t.x,h0,l0); split2(t.y,h1,l1); split2(t.z,h2,l2); split2(t.w,h3,l3);
        *(u32*)(smc+Q_PKH+off)   = (u32)h0 | ((u32)h1<<16);
        *(u32*)(smc+Q_PKH+off+4) = (u32)h2 | ((u32)h3<<16);
        *(u32*)(smc+Q_PKL+off)   = (u32)l0 | ((u32)l1<<16);
        *(u32*)(smc+Q_PKL+off+4) = (u32)l2 | ((u32)l3<<16);
    }

    #pragma unroll
    for (int it = 0; it < 4; it++) {
        int t4 = it*256 + tid;
        int jp = t4 >> 4, dg = (t4 & 15) << 2;
        float4 va = *reinterpret_cast<const float4*>(vg + (tok0 + 2*jp)*Dd + dg);
        float4 vb = *reinterpret_cast<const float4*>(vg + (tok0 + 2*jp + 1)*Dd + dg);
        float fa[4] = {va.x, va.y, va.z, va.w};
        float fb[4] = {vb.x, vb.y, vb.z, vb.w};
        #pragma unroll
        for (int e = 0; e < 4; e++) {
            u16 ha,la,hb,lb;
            split2(fa[e], ha, la); split2(fb[e], hb, lb);
            u32 off = (u32)(dg+e) * SR + (u32)jp * 4;
            *(u32*)(smc+Q_VTH+off) = (u32)ha | ((u32)hb<<16);
            *(u32*)(smc+Q_VTL+off) = (u32)la | ((u32)lb<<16);
        }
    }
    __syncthreads();

    {
        int m = tid & 127, ih = tid >> 7;
        float s = 0.f;
        int ibase = ih * 64;
        #pragma unroll 8
        for (int i = 0; i < 64; i++) {
            u32 off = (u32)(ibase + i) * SR + (u32)m * 2;
            s += bf2f(*(u16*)(smc+Q_PKH+off)) + bf2f(*(u16*)(smc+Q_PKL+off));
        }
        zp[tid] = s;
    }
    __syncthreads();
    if (tid < 128) d_zz[(bh*NC + c)*Mm + tid] = zp[tid] + zp[tid + 128];

    const int dt = wid >> 1, mh = wid & 1;
    const int d0 = dt * 16;
    float acc[8][4];
    #pragma unroll
    for (int t = 0; t < 8; t++)
        #pragma unroll
        for (int e = 0; e < 4; e++) acc[t][e] = 0.f;

    for (int kk = 0; kk < 8; kk++) {
        int k0 = kk * 16;
        u32 ah0,ah1,ah2,ah3, al0,al1,al2,al3;
        ldsm4(ah0,ah1,ah2,ah3, a_addr(sb+Q_VTH, d0, k0, lane));
        ldsm4(al0,al1,al2,al3, a_addr(sb+Q_VTL, d0, k0, lane));
        #pragma unroll
        for (int t = 0; t < 8; t++) {
            int n0 = (mh*8 + t) * 8;
            u32 bh0,bh1, bl0,bl1;
            ldsm2t(bh0,bh1, bt_addr(sb+Q_PKH, n0, k0, lane));
            ldsm2t(bl0,bl1, bt_addr(sb+Q_PKL, n0, k0, lane));
            mma16816(acc[t], ah0,ah1,ah2,ah3, bh0,bh1);
            mma16816(acc[t], ah0,ah1,ah2,ah3, bl0,bl1);
            mma16816(acc[t], al0,al1,al2,al3, bh0,bh1);
        }
    }

    float* SgT = d_S + (size_t)(bh*NC + c) * (Mm*Dd);
    const int d1 = d0 + (lane >> 2), d2 = d1 + 8;
    #pragma unroll
    for (int t = 0; t < 8; t++) {
        int m = (mh*8 + t)*8 + 2*(lane & 3);
        float2 t1 = { acc[t][0], acc[t][1] };
        float2 t2 = { acc[t][2], acc[t][3] };
        *reinterpret_cast<float2*>(SgT + d1*Mm + m) = t1;
        *reinterpret_cast<float2*>(SgT + d2*Mm + m) = t2;
    }
}

// ---------------------------------------------------------------------------
// K3: exclusive prefix over the 32 chunks (R15)
// ---------------------------------------------------------------------------
__global__ __launch_bounds__(256) void k_scan() {
    const int gid = blockIdx.x * 256 + threadIdx.x;
    if (blockIdx.x < 2048) {
        const int bh = gid >> 13;
        const int e  = gid & 8191;
        const size_t p = (size_t)bh * NC * (Mm*Dd) + e;
        float v[NC];
        #pragma unroll
        for (int c = 0; c < NC; c++) v[c] = d_S[p + (size_t)c * (Mm*Dd)];
        float acc = 0.f;
        #pragma unroll
        for (int c = 0; c < NC; c++) {
            d_S[p + (size_t)c * (Mm*Dd)] = acc;
            acc += v[c];
        }
    } else {
        const int idx = gid - 2048*256;
        const int bh = idx >> 7, m = idx & 127;
        const size_t p = (size_t)bh * NC * Mm + m;
        float v[NC];
        #pragma unroll
        for (int c = 0; c < NC; c++) v[c] = d_zz[p + c*Mm];
        float acc = 0.f;
        #pragma unroll
        for (int c = 0; c < NC; c++) {
            d_zz[p + c*Mm] = acc;
            acc += v[c];
        }
    }
}

// ---------------------------------------------------------------------------
// K4 (warp-MMA, 1024 threads / 32 warps): 4 warps share an i-block (pid),
// splitting n 4-ways (qrt). q-projection fused (R15). 8 warps/SMSP.
// ---------------------------------------------------------------------------
#define OF_RM  0      // 2048 B: rowmax exchange [128][4], later den[128]
#define SQ_HI  2048
#define SQ_LO  (SQ_HI + 34816)
#define SK_HI  (SQ_LO + 34816)
#define SK_LO  (SK_HI + 34816)
#define SV_HI  (SK_LO + 34816)
#define SV_LO  (SV_HI + 19584)
#define SS_HI  (SV_LO + 19584)
#define SS_LO  (SS_HI + 19584)
#define SM4T   (SS_LO + 19584)   // 219648 bytes

__global__ __launch_bounds__(1024) void k_out_mma(const float* __restrict__ qg,
                                                  const float* __restrict__ omg,
                                                  const float* __restrict__ vg,
                                                  float* __restrict__ outg) {
    extern __shared__ char smc[];
    const u32 sb = s2u(smc);
    float* rm_s  = (float*)(smc + OF_RM);
    const int tid = threadIdx.x, wid = tid >> 5, lane = tid & 31;
    const int pid = wid & 7, qrt = wid >> 3;   // i-block + n-quarter
    const int bid = blockIdx.x, bh = bid >> 5, c = bid & 31;
    const size_t tok0 = (size_t)bh * Nn + (size_t)c * CH;
    const float gm = d_gmax;

    // ---- phase A: stage q (scaled, split) -> SQ; omega -> SK ----
    const float* xg = qg + tok0 * Dd;
    #pragma unroll
    for (int it = 0; it < 2; it++) {
        int f4g = it*1024 + tid;               // 0..2047 float4s
        int r = f4g >> 4, c4 = (f4g & 15) * 4;
        u32 off = (u32)r * SR + (u32)c4 * 2;
        float4 t = *reinterpret_cast<const float4*>(xg + r*Dd + c4);
        t.x *= SCALE; t.y *= SCALE; t.z *= SCALE; t.w *= SCALE;
        u16 h0,l0,h1,l1,h2,l2,h3,l3;
        split2(t.x,h0,l0); split2(t.y,h1,l1); split2(t.z,h2,l2); split2(t.w,h3,l3);
        *(u32*)(smc+SQ_HI+off)   = (u32)h0 | ((u32)h1<<16);
        *(u32*)(smc+SQ_HI+off+4) = (u32)h2 | ((u32)h3<<16);
        *(u32*)(smc+SQ_LO+off)   = (u32)l0 | ((u32)l1<<16);
        *(u32*)(smc+SQ_LO+off+4) = (u32)l2 | ((u32)l3<<16);
        float4 w = *reinterpret_cast<const float4*>(omg + (size_t)f4g * 4);
        split2(w.x,h0,l0); split2(w.y,h1,l1); split2(w.z,h2,l2); split2(w.w,h3,l3);
        *(u32*)(smc+SK_HI+off)   = (u32)h0 | ((u32)h1<<16);
        *(u32*)(smc+SK_HI+off+4) = (u32)h2 | ((u32)h3<<16);
        *(u32*)(smc+SK_LO+off)   = (u32)l0 | ((u32)l1<<16);
        *(u32*)(smc+SK_LO+off+4) = (u32)l2 | ((u32)l3<<16);
    }
    __syncthreads();

    // ---- phase B: proj GEMM (rows pid*16, m-quarter = qrt*32) ----
    {
        const int prow = pid * 16;
        float pacc[4][4];
        #pragma unroll
        for (int t = 0; t < 4; t++)
            #pragma unroll
            for (int e = 0; e < 4; e++) pacc[t][e] = 0.f;

        #pragma unroll
        for (int kk = 0; kk < 4; kk++) {
            int k0 = kk * 16;
            u32 xh0,xh1,xh2,xh3, xl0,xl1,xl2,xl3;
            ldsm4(xh0,xh1,xh2,xh3, a_addr(sb+SQ_HI, prow, k0, lane));
            ldsm4(xl0,xl1,xl2,xl3, a_addr(sb+SQ_LO, prow, k0, lane));
            #pragma unroll
            for (int t = 0; t < 4; t++) {
                int nt = qrt*4 + t;
                u32 oh0,oh1, ol0,ol1;
                ldsm2(oh0,oh1, b_addr(sb+SK_HI, nt*8, k0, lane));
                ldsm2(ol0,ol1, b_addr(sb+SK_LO, nt*8, k0, lane));
                mma16816(pacc[t], xh0,xh1,xh2,xh3, oh0,oh1);
                mma16816(pacc[t], xh0,xh1,xh2,xh3, ol0,ol1);
                mma16816(pacc[t], xl0,xl1,xl2,xl3, oh0,oh1);
            }
        }

        const int m1 = prow + (lane >> 2);
        const int m2 = m1 + 8;
        float rm1 = -3.0e38f, rm2 = -3.0e38f;
        #pragma unroll
        for (int t = 0; t < 4; t++) {
            rm1 = fmaxf(rm1, fmaxf(pacc[t][0], pacc[t][1]));
            rm2 = fmaxf(rm2, fmaxf(pacc[t][2], pacc[t][3]));
        }
        rm1 = fmaxf(rm1, __shfl_xor_sync(0xFFFFFFFFu, rm1, 1));
        rm1 = fmaxf(rm1, __shfl_xor_sync(0xFFFFFFFFu, rm1, 2));
        rm2 = fmaxf(rm2, __shfl_xor_sync(0xFFFFFFFFu, rm2, 1));
        rm2 = fmaxf(rm2, __shfl_xor_sync(0xFFFFFFFFu, rm2, 2));
        if ((lane & 3) == 0) {
            rm_s[m1*4 + qrt] = rm1;
            rm_s[m2*4 + qrt] = rm2;
        }
        __syncthreads();
        rm1 = fmaxf(fmaxf(rm_s[m1*4], rm_s[m1*4+1]), fmaxf(rm_s[m1*4+2], rm_s[m1*4+3]));
        rm2 = fmaxf(fmaxf(rm_s[m2*4], rm_s[m2*4+1]), fmaxf(rm_s[m2*4+2], rm_s[m2*4+3]));

        // exp -> phi_q split, overwrite SQ tiles (own rows/cols)
        #pragma unroll
        for (int t = 0; t < 4; t++) {
            int jj = (qrt*4 + t)*8 + 2*(lane & 3);
            float p0 = __expf(pacc[t][0]-rm1)*INV_SQRT_M + EPS_PHI;
            float p1 = __expf(pacc[t][1]-rm1)*INV_SQRT_M + EPS_PHI;
            float p2 = __expf(pacc[t][2]-rm2)*INV_SQRT_M + EPS_PHI;
            float p3 = __expf(pacc[t][3]-rm2)*INV_SQRT_M + EPS_PHI;
            u16 h0,l0,h1,l1;
            split2(p0, h0, l0); split2(p1, h1, l1);
            u32 off = (u32)m1 * SR + (u32)jj * 2;
            *(u32*)(smc+SQ_HI+off) = (u32)h0 | ((u32)h1<<16);
            *(u32*)(smc+SQ_LO+off) = (u32)l0 | ((u32)l1<<16);
            split2(p2, h0, l0); split2(p3, h1, l1);
            off = (u32)m2 * SR + (u32)jj * 2;
            *(u32*)(smc+SQ_HI+off) = (u32)h0 | ((u32)h1<<16);
            *(u32*)(smc+SQ_LO+off) = (u32)l0 | ((u32)l1<<16);
        }
    }
    __syncthreads();   // omega reads + phi_q writes complete

    // ---- phase C: stage phi_k (exp from lp) -> SK, V -> SV, S^T -> SS ----
    const float* pkg = d_phik + tok0 * Mm;
    #pragma unroll
    for (int it = 0; it < 4; it++) {
        int idx = (it*1024 + tid) * 4;
        int r = idx >> 7, cc = idx & 127;
        u32 off = (u32)r * SR + (u32)cc * 2;
        float4 t = *reinterpret_cast<const float4*>(pkg + idx);
        t.x = __expf(t.x-gm)*INV_SQRT_M + EPS_PHI;
        t.y = __expf(t.y-gm)*INV_SQRT_M + EPS_PHI;
        t.z = __expf(t.z-gm)*INV_SQRT_M + EPS_PHI;
        t.w = __expf(t.w-gm)*INV_SQRT_M + EPS_PHI;
        u16 h0,l0,h1,l1,h2,l2,h3,l3;
        split2(t.x,h0,l0); split2(t.y,h1,l1); split2(t.z,h2,l2); split2(t.w,h3,l3);
        *(u32*)(smc+SK_HI+off)   = (u32)h0 | ((u32)h1<<16);
        *(u32*)(smc+SK_HI+off+4) = (u32)h2 | ((u32)h3<<16);
        *(u32*)(smc+SK_LO+off)   = (u32)l0 | ((u32)l1<<16);
        *(u32*)(smc+SK_LO+off+4) = (u32)l2 | ((u32)l3<<16);
    }

    {   // V^T staging: 1024 t4 entries == blockDim, single pass
        int jp = tid >> 4, dg = (tid & 15) << 2;
        float4 va = *reinterpret_cast<const float4*>(vg + (tok0 + 2*jp)*Dd + dg);
        float4 vb = *reinterpret_cast<const float4*>(vg + (tok0 + 2*jp + 1)*Dd + dg);
        float fa[4] = {va.x, va.y, va.z, va.w};
        float fb[4] = {vb.x, vb.y, vb.z, vb.w};
        #pragma unroll
        for (int e = 0; e < 4; e++) {
            u16 ha,la,hb,lb;
            split2(fa[e], ha, la); split2(fb[e], hb, lb);
            u32 off = (u32)(dg+e) * SR + (u32)jp * 4;
            *(u32*)(smc+SV_HI+off) = (u32)ha | ((u32)hb<<16);
            *(u32*)(smc+SV_LO+off) = (u32)la | ((u32)lb<<16);
        }
    }
    {
        const float* SgT = d_S + (size_t)(bh*NC + c) * (Mm*Dd);
        #pragma unroll
        for (int it = 0; it < 2; it++) {
            int idx = (it*1024 + tid) * 4;
            int d = idx >> 7, m = idx & 127;
            u32 off = (u32)d * SR + (u32)m * 2;
            float4 t = *reinterpret_cast<const float4*>(SgT + idx);
            u16 h0,l0,h1,l1,h2,l2,h3,l3;
            split2(t.x,h0,l0); split2(t.y,h1,l1); split2(t.z,h2,l2); split2(t.w,h3,l3);
            *(u32*)(smc+SS_HI+off)   = (u32)h0 | ((u32)h1<<16);
            *(u32*)(smc+SS_HI+off+4) = (u32)h2 | ((u32)h3<<16);
            *(u32*)(smc+SS_LO+off)   = (u32)l0 | ((u32)l1<<16);
            *(u32*)(smc+SS_LO+off+4) = (u32)l2 | ((u32)l3<<16);
        }
    }
    if (tid < 64) {
        int cp = tid * 2;
        u32 off = 64u * SR + (u32)tid * 4;
        *(u32*)(smc+SV_HI+off) = 0x3F803F80u;
        *(u32*)(smc+SV_LO+off) = 0u;
        const float* zg = d_zz + (bh*NC + c) * Mm;
        u16 h0,l0,h1,l1;
        split2(zg[cp],   h0, l0);
        split2(zg[cp+1], h1, l1);
        *(u32*)(smc+SS_HI+off) = (u32)h0 | ((u32)h1<<16);
        *(u32*)(smc+SS_LO+off) = (u32)l0 | ((u32)l1<<16);
    }
    for (int t4 = tid; t4 < 7*64; t4 += 1024) {
        int r = 65 + t4/64;
        u32 off = (u32)r * SR + (u32)(t4 % 64) * 4;
        *(u32*)(smc+SV_HI+off) = 0u;
        *(u32*)(smc+SV_LO+off) = 0u;
        *(u32*)(smc+SS_HI+off) = 0u;
        *(u32*)(smc+SS_LO+off) = 0u;
    }
    __syncthreads();

    const int ib = (pid < 4) ? pid : (7 - (pid - 4));
    const int i0 = ib * 16;
    const int ntmax1 = 2*ib + 1;

    // ---- GEMM1: A = phiq . phik^T, tiles nt = 4s+qrt, nt <= ntmax1 ----
    float acc[4][4];
    #pragma unroll
    for (int s = 0; s < 4; s++)
        #pragma unroll
        for (int e = 0; e < 4; e++) acc[s][e] = 0.f;

    for (int kk = 0; kk < 8; kk++) {
        int k0 = kk * 16;
        u32 qh0,qh1,qh2,qh3, ql0,ql1,ql2,ql3;
        ldsm4(qh0,qh1,qh2,qh3, a_addr(sb+SQ_HI, i0, k0, lane));
        ldsm4(ql0,ql1,ql2,ql3, a_addr(sb+SQ_LO, i0, k0, lane));
        #pragma unroll
        for (int s = 0; s < 4; s++) {
            int nt = 4*s + qrt;
            if (nt <= ntmax1) {
                u32 bh0,bh1, bl0,bl1;
                ldsm2(bh0,bh1, b_addr(sb+SK_HI, nt*8, k0, lane));
                ldsm2(bl0,bl1, b_addr(sb+SK_LO, nt*8, k0, lane));
                mma16816(acc[s], qh0,qh1,qh2,qh3, bh0,bh1);
                mma16816(acc[s], qh0,qh1,qh2,qh3, bl0,bl1);
                mma16816(acc[s], ql0,ql1,ql2,ql3, bh0,bh1);
            }
        }
    }

    __syncthreads();   // all warps done reading phik tiles

    // ---- mask causal, split, overwrite phik tiles (own tiles) ----
    {
        const int m1 = i0 + (lane >> 2);
        const int m2 = m1 + 8;
        #pragma unroll
        for (int s = 0; s < 4; s++) {
            int nt = 4*s + qrt;
            if (nt <= ntmax1) {
                int jj = nt*8 + 2*(lane & 3);
                float a0 = (jj     <= m1) ? acc[s][0] : 0.f;
                float a1 = (jj + 1 <= m1) ? acc[s][1] : 0.f;
                float a2 = (jj     <= m2) ? acc[s][2] : 0.f;
                float a3 = (jj + 1 <= m2) ? acc[s][3] : 0.f;
                u16 h0,l0,h1,l1;
                split2(a0, h0, l0); split2(a1, h1, l1);
                u32 off = (u32)m1 * SR + (u32)jj * 2;
                *(u32*)(smc+SK_HI+off) = (u32)h0 | ((u32)h1<<16);
                *(u32*)(smc+SK_LO+off) = (u32)l0 | ((u32)l1<<16);
                split2(a2, h0, l0); split2(a3, h1, l1);
                off = (u32)m2 * SR + (u32)jj * 2;
                *(u32*)(smc+SK_HI+off) = (u32)h0 | ((u32)h1<<16);
                *(u32*)(smc+SK_LO+off) = (u32)l0 | ((u32)l1<<16);
            }
        }
    }
    __syncthreads();

    // ---- GEMM2: D2 = A.VT + phiq.ST, tiles {qrt, qrt+4}, den on qrt==3 ----
    float o[3][4];
    #pragma unroll
    for (int s = 0; s < 3; s++)
        #pragma unroll
        for (int e = 0; e < 4; e++) o[s][e] = 0.f;

    for (int kk = 0; kk < 8; kk++) {
        int k0 = kk * 16;
        u32 qh0,qh1,qh2,qh3, ql0,ql1,ql2,ql3;
        ldsm4(qh0,qh1,qh2,qh3, a_addr(sb+SQ_HI, i0, k0, lane));
        ldsm4(ql0,ql1,ql2,ql3, a_addr(sb+SQ_LO, i0, k0, lane));
        const bool doA = (kk <= ib);
        u32 ah0=0,ah1=0,ah2=0,ah3=0, al0=0,al1=0,al2=0,al3=0;
        if (doA) {
            ldsm4(ah0,ah1,ah2,ah3, a_addr(sb+SK_HI, i0, k0, lane));
            ldsm4(al0,al1,al2,al3, a_addr(sb+SK_LO, i0, k0, lane));
        }
        #pragma unroll
        for (int t = 0; t < 2; t++) {
            int nt = qrt + 4*t;
            u32 sh0,sh1, sl0,sl1;
            ldsm2(sh0,sh1, b_addr(sb+SS_HI, nt*8, k0, lane));
            ldsm2(sl0,sl1, b_addr(sb+SS_LO, nt*8, k0, lane));
            mma16816(o[t], qh0,qh1,qh2,qh3, sh0,sh1);
            mma16816(o[t], qh0,qh1,qh2,qh3, sl0,sl1);
            mma16816(o[t], ql0,ql1,ql2,ql3, sh0,sh1);
            if (doA) {
                u32 vh0,vh1, vl0,vl1;
                ldsm2(vh0,vh1, b_addr(sb+SV_HI, nt*8, k0, lane));
                ldsm2(vl0,vl1, b_addr(sb+SV_LO, nt*8, k0, lane));
                mma16816(o[t], ah0,ah1,ah2,ah3, vh0,vh1);
                mma16816(o[t], ah0,ah1,ah2,ah3, vl0,vl1);
                mma16816(o[t], al0,al1,al2,al3, vh0,vh1);
            }
        }
        if (qrt == 3) {   // den tile 8 (warp-uniform branch)
            u32 sh0,sh1, sl0,sl1;
            ldsm2(sh0,sh1, b_addr(sb+SS_HI, 64, k0, lane));
            ldsm2(sl0,sl1, b_addr(sb+SS_LO, 64, k0, lane));
            mma16816(o[2], qh0,qh1,qh2,qh3, sh0,sh1);
            mma16816(o[2], qh0,qh1,qh2,qh3, sl0,sl1);
            mma16816(o[2], ql0,ql1,ql2,ql3, sh0,sh1);
            if (doA) {
                u32 vh0,vh1, vl0,vl1;
                ldsm2(vh0,vh1, b_addr(sb+SV_HI, 64, k0, lane));
                ldsm2(vl0,vl1, b_addr(sb+SV_LO, 64, k0, lane));
                mma16816(o[2], ah0,ah1,ah2,ah3, vh0,vh1);
                mma16816(o[2], ah0,ah1,ah2,ah3, vl0,vl1);
                mma16816(o[2], al0,al1,al2,al3, vh0,vh1);
            }
        }
    }

    if (qrt == 3 && (lane & 3) == 0) {
        rm_s[i0 + (lane >> 2)]     = 1.f / (o[2][0] + EPS_DEN);
        rm_s[i0 + 8 + (lane >> 2)] = 1.f / (o[2][2] + EPS_DEN);
    }
    __syncthreads();
    {
        const int m1 = i0 + (lane >> 2);
        const int m2 = m1 + 8;
        const float inv1 = rm_s[m1];
        const float inv2 = rm_s[m2];
        #pragma unroll
        for (int t = 0; t < 2; t++) {
            int n = (qrt + 4*t)*8 + 2*(lane & 3);
            float2 t1 = { o[t][0]*inv1, o[t][1]*inv1 };
            float2 t2 = { o[t][2]*inv2, o[t][3]*inv2 };
            *reinterpret_cast<float2*>(outg + (tok0 + m1)*Dd + n) = t1;
            *reinterpret_cast<float2*>(outg + (tok0 + m2)*Dd + n) = t2;
        }
    }
}

// ---------------------------------------------------------------------------

extern "C" void kernel_launch(void* const* d_in, const int* in_sizes, int n_in,
                              void* d_out, int out_size) {
    const float* q  = (const float*)d_in[0];
    const float* k  = (const float*)d_in[1];
    const float* v  = (const float*)d_in[2];
    const float* om = (const float*)d_in[3];
    float* out = (float*)d_out;

    cudaFuncSetAttribute(k_proj_mma, cudaFuncAttributeMaxDynamicSharedMemorySize, SM1T);
    cudaFuncSetAttribute(k_sums_mma, cudaFuncAttributeMaxDynamicSharedMemorySize, SM2T);
    cudaFuncSetAttribute(k_out_mma,  cudaFuncAttributeMaxDynamicSharedMemorySize, SM4T);

    k_proj_mma<<<NBT, 256, SM1T>>>(k, om);
    k_gmax<<<1, 256>>>();
    k_sums_mma<<<NBT, 256, SM2T>>>(v);
    k_scan<<<2048 + 32, 256>>>();
    k_out_mma<<<NBT, 1024, SM4T>>>(q, om, v, out);
}